// round 10
// baseline (speedup 1.0000x reference)
#include <cuda_runtime.h>
#include <cuda_bf16.h>
#include <math_constants.h>
#include <cstdint>

#define BB 4
#define NN 256
#define DD 128
#define HH 256          // 2*D
#define BN (BB*NN)      // 1024 rows

// ---------------------------------------------------------------------------
// Device scratch
// ---------------------------------------------------------------------------
__device__ float g_Amat[BN * HH];     // A[row,h] = s_row @ W1a + b1
__device__ float g_Bmat[BN * HH];     // B[row,h] = s_row @ W1b
__device__ float g_scores[BB * NN * NN];
__device__ float4 g_Bh_img[4096];     // 64KB: W1c^T hi, [h][d] bf16, seg-swizzled
__device__ float4 g_Bl_img[4096];     // 64KB: lo part

// ---------------------------------------------------------------------------
// helpers
// ---------------------------------------------------------------------------
__device__ __forceinline__ uint32_t smem_u32(const void* p) {
    uint32_t a;
    asm("{ .reg .u64 t; cvta.to.shared.u64 t, %1; cvt.u32.u64 %0, t; }"
        : "=r"(a) : "l"(p));
    return a;
}
__device__ __forceinline__ void ldsm_x4(uint32_t& r0, uint32_t& r1,
                                        uint32_t& r2, uint32_t& r3, uint32_t a) {
    asm volatile("ldmatrix.sync.aligned.m8n8.x4.shared.b16 {%0,%1,%2,%3}, [%4];"
                 : "=r"(r0), "=r"(r1), "=r"(r2), "=r"(r3) : "r"(a));
}
__device__ __forceinline__ void ldsm_x2(uint32_t& r0, uint32_t& r1, uint32_t a) {
    asm volatile("ldmatrix.sync.aligned.m8n8.x2.shared.b16 {%0,%1}, [%2];"
                 : "=r"(r0), "=r"(r1) : "r"(a));
}
__device__ __forceinline__ void mma16816(float* d, uint32_t a0, uint32_t a1,
                                         uint32_t a2, uint32_t a3,
                                         uint32_t b0, uint32_t b1) {
    asm volatile(
        "mma.sync.aligned.m16n8k16.row.col.f32.bf16.bf16.f32 "
        "{%0,%1,%2,%3}, {%4,%5,%6,%7}, {%8,%9}, {%0,%1,%2,%3};"
        : "+f"(d[0]), "+f"(d[1]), "+f"(d[2]), "+f"(d[3])
        : "r"(a0), "r"(a1), "r"(a2), "r"(a3), "r"(b0), "r"(b1));
}

// ---------------------------------------------------------------------------
// Kernel 1: precompute A,B (proven config)
// ---------------------------------------------------------------------------
#define PR 4
__global__ void __launch_bounds__(256)
precompute_AB_kernel(const float* __restrict__ s,
                     const float* __restrict__ W1,
                     const float* __restrict__ b1) {
    __shared__ float  sv[PR][DD];
    __shared__ float4 WA4[2][16 * 64];
    __shared__ float4 WB4[2][16 * 64];

    const int row0 = blockIdx.x * PR;
    const int tid = threadIdx.x;

    for (int idx = tid; idx < PR * DD; idx += 256)
        sv[idx >> 7][idx & 127] = s[row0 * DD + idx];

    const float bias = b1[tid];
    float a[PR], bb[PR];
#pragma unroll
    for (int r = 0; r < PR; r++) { a[r] = bias; bb[r] = 0.f; }

    const float4* W1_4 = (const float4*)W1;

    float4 pa[4], pb[4];
#pragma unroll
    for (int k = 0; k < 4; k++) {
        int idx = k * 256 + tid;
        int d = idx >> 6, c = idx & 63;
        pa[k] = __ldg(&W1_4[d * 64 + c]);
        pb[k] = __ldg(&W1_4[(DD + d) * 64 + c]);
    }

    for (int ch = 0; ch < 8; ch++) {
        const int buf = ch & 1;
        __syncthreads();
#pragma unroll
        for (int k = 0; k < 4; k++) {
            WA4[buf][k * 256 + tid] = pa[k];
            WB4[buf][k * 256 + tid] = pb[k];
        }
        if (ch < 7) {
            const int d0 = (ch + 1) * 16;
#pragma unroll
            for (int k = 0; k < 4; k++) {
                int idx = k * 256 + tid;
                int d = idx >> 6, c = idx & 63;
                pa[k] = __ldg(&W1_4[(d0 + d) * 64 + c]);
                pb[k] = __ldg(&W1_4[(DD + d0 + d) * 64 + c]);
            }
        }
        __syncthreads();
        const float* WA = (const float*)WA4[buf];
        const float* WB = (const float*)WB4[buf];
        const int d0 = ch * 16;
#pragma unroll
        for (int dd = 0; dd < 16; dd++) {
            float wa = WA[dd * 256 + tid];
            float wb = WB[dd * 256 + tid];
#pragma unroll
            for (int r = 0; r < PR; r++) {
                float sval = sv[r][d0 + dd];
                a[r]  = fmaf(sval, wa, a[r]);
                bb[r] = fmaf(sval, wb, bb[r]);
            }
        }
    }
#pragma unroll
    for (int r = 0; r < PR; r++) {
        g_Amat[(row0 + r) * HH + tid] = a[r];
        g_Bmat[(row0 + r) * HH + tid] = bb[r];
    }
}

// ---------------------------------------------------------------------------
// Kernel 1b: split W1c -> bf16 hi/lo global images, laid out exactly as the
// main kernel's B smem: [h][d] bf16 rows of 256B, 16B segments XOR-swizzled
// by (h&7) so ldmatrix row reads are conflict-free.
// ---------------------------------------------------------------------------
__global__ void __launch_bounds__(256)
split_w1c_kernel(const float* __restrict__ W1) {
    int idx = blockIdx.x * 256 + threadIdx.x;   // 0..32767
    int d = idx >> 8, h = idx & 255;
    float w = W1[(2 * DD + d) * HH + h];
    __nv_bfloat16 hi = __float2bfloat16_rn(w);
    float r = w - __bfloat162float(hi);
    __nv_bfloat16 lo = __float2bfloat16_rn(r);
    uint32_t byte = (uint32_t)h * 256u
                  + (uint32_t)(((d >> 3) ^ (h & 7)) << 4)
                  + (uint32_t)((d & 7) << 1);
    *(__nv_bfloat16*)((char*)g_Bh_img + byte) = hi;
    *(__nv_bfloat16*)((char*)g_Bl_img + byte) = lo;
}

// ---------------------------------------------------------------------------
// Kernel 2: persistent mma.sync bf16 kernel.
// Item = (b, i, jtile): D[j(128), h(256)] = sum_d (s_i*s_j)[d] * W1c[d,h],
// 3 bf16 split passes accumulated in fp32 register fragments
// (Ah*Bh + Ah*Bl + Al*Bh; dropped Al*Bl term <= 2^-18 relative).
// 8 warps x m16 j-tiles; N processed in two 128-h halves (acc 64 regs).
// Fused epilogue: score[j] += relu(D + Ai[h] + Bmat[j][h]) * W2[h].
// ---------------------------------------------------------------------------
#define GRID_MAIN 148
#define N_ITEMS   (BB * NN * 2)   // 2048

#define OFF_BH 0          // 65536
#define OFF_BL 65536      // 65536
#define OFF_AH 131072     // 32768
#define OFF_AL 163840     // 32768
#define OFF_AI 196608     // 1024
#define OFF_W2 197632     // 1024
#define OFF_SI 198656     // 512
#define SMEM_MAIN 199168

__global__ void __launch_bounds__(256)
mma_main_kernel(const float* __restrict__ s, const float* __restrict__ W2) {
    extern __shared__ char smc[];
    float* aiS = (float*)(smc + OFF_AI);
    float* w2S = (float*)(smc + OFF_W2);
    float* siS = (float*)(smc + OFF_SI);

    const int tid  = threadIdx.x;
    const int warp = tid >> 5;
    const int lane = tid & 31;
    const int bid  = blockIdx.x;
    const uint32_t sbase = smem_u32(smc);

    // Stage B hi/lo images once (resident across all items)
    {
        float4* bh = (float4*)(smc + OFF_BH);
        float4* bl = (float4*)(smc + OFF_BL);
        for (int k = tid; k < 4096; k += 256) {
            bh[k] = __ldg(&g_Bh_img[k]);
            bl[k] = __ldg(&g_Bl_img[k]);
        }
        w2S[tid] = __ldg(&W2[tid]);
    }
    __syncthreads();

    // ldmatrix lane constants
    const int l7  = lane & 7;
    const int g   = lane >> 3;            // A: 4 address groups
    const int shA = g >> 1;               // A k-segment select
    const int rowA = warp * 16 + ((g & 1) << 3) + l7;
    const uint32_t aBaseH = sbase + OFF_AH + (uint32_t)rowA * 256u;
    const uint32_t aBaseL = aBaseH + (uint32_t)(OFF_AL - OFF_AH);
    const int l16 = lane & 15;
    const int shB = l16 >> 3;             // B k-segment select
    const uint32_t bRowOff = (uint32_t)(l16 & 7) * 256u;
    const uint32_t bBaseH = sbase + OFF_BH + bRowOff;
    const uint32_t bBaseL = bBaseH + (uint32_t)(OFF_BL - OFF_BH);
    const uint32_t bXor = (uint32_t)(l16 & 7);
    const uint32_t aXor = (uint32_t)l7;

    const int n = (N_ITEMS - 1 - bid) / GRID_MAIN + 1;

    for (int u = 0; u < n; u++) {
        const int t  = bid + u * GRID_MAIN;
        const int b  = t >> 9;
        const int i  = (t >> 1) & 255;
        const int jt = t & 1;
        const int brow = b * NN;

        __syncthreads();   // previous item fully consumed
        if (tid < DD) siS[tid] = s[(size_t)(brow + i) * DD + tid];
        aiS[tid] = g_Amat[(size_t)(brow + i) * HH + tid];
        __syncthreads();

        // Stage A = (s_i o s_j) split hi/lo, swizzled. 2 threads per j row.
        {
            const int j  = tid >> 1;
            const int dh = tid & 1;
            const float* srow  = s + (size_t)(brow + jt * 128 + j) * DD + dh * 64;
            const float* sivec = siS + dh * 64;
            const uint32_t rbase = (uint32_t)j * 256u;
            const uint32_t jx = (uint32_t)(j & 7);
#pragma unroll 8
            for (int dp = 0; dp < 32; dp++) {
                const int d = dh * 64 + dp * 2;
                float2 sj = __ldg((const float2*)(srow + dp * 2));
                float2 si = *(const float2*)(sivec + dp * 2);
                float a0 = si.x * sj.x, a1 = si.y * sj.y;
                __nv_bfloat16 h0 = __float2bfloat16_rn(a0);
                __nv_bfloat16 h1 = __float2bfloat16_rn(a1);
                float r0 = a0 - __bfloat162float(h0);
                float r1 = a1 - __bfloat162float(h1);
                uint32_t off = rbase + ((((uint32_t)(d >> 3)) ^ jx) << 4)
                             + (uint32_t)((d & 7) << 1);
                *(__nv_bfloat162*)(smc + OFF_AH + off) = __halves2bfloat162(h0, h1);
                *(__nv_bfloat162*)(smc + OFF_AL + off) =
                    __halves2bfloat162(__float2bfloat16_rn(r0),
                                       __float2bfloat16_rn(r1));
            }
        }
        __syncthreads();

        float p0 = 0.f, p1 = 0.f;
        const int jg0 = jt * 128 + warp * 16 + (lane >> 2);
        const float* bjr0 = g_Bmat + (size_t)(brow + jg0) * HH;
        const float* bjr1 = bjr0 + 8 * HH;

#pragma unroll 1
        for (int half = 0; half < 2; half++) {
            float acc[16][4];
#pragma unroll
            for (int nc = 0; nc < 16; nc++)
#pragma unroll
                for (int q = 0; q < 4; q++) acc[nc][q] = 0.f;

            const uint32_t hOff = (uint32_t)(half * 128) * 256u;

#pragma unroll 1
            for (int kc = 0; kc < 8; kc++) {
                uint32_t ah0, ah1, ah2, ah3, al0, al1, al2, al3;
                const uint32_t aSw = (((uint32_t)(2 * kc + shA)) ^ aXor) << 4;
                ldsm_x4(ah0, ah1, ah2, ah3, aBaseH + aSw);
                ldsm_x4(al0, al1, al2, al3, aBaseL + aSw);
                const uint32_t bSw = (((uint32_t)(2 * kc + shB)) ^ bXor) << 4;
#pragma unroll
                for (int nc = 0; nc < 16; nc++) {
                    const uint32_t bo = hOff + (uint32_t)(nc * 8) * 256u + bSw;
                    uint32_t bh0, bh1, bl0, bl1;
                    ldsm_x2(bh0, bh1, bBaseH + bo);
                    ldsm_x2(bl0, bl1, bBaseL + bo);
                    mma16816(acc[nc], ah0, ah1, ah2, ah3, bh0, bh1);
                    mma16816(acc[nc], ah0, ah1, ah2, ah3, bl0, bl1);
                    mma16816(acc[nc], al0, al1, al2, al3, bh0, bh1);
                }
            }

            // epilogue for this h-half
            const int hb = half * 128 + 2 * (lane & 3);
#pragma unroll
            for (int nc = 0; nc < 16; nc++) {
                const int h0 = hb + nc * 8;
                float2 ai = *(const float2*)(aiS + h0);
                float2 w2 = *(const float2*)(w2S + h0);
                float2 bv0 = __ldg((const float2*)(bjr0 + h0));
                float2 bv1 = __ldg((const float2*)(bjr1 + h0));
                p0 = fmaf(fmaxf(acc[nc][0] + ai.x + bv0.x, 0.f), w2.x, p0);
                p0 = fmaf(fmaxf(acc[nc][1] + ai.y + bv0.y, 0.f), w2.y, p0);
                p1 = fmaf(fmaxf(acc[nc][2] + ai.x + bv1.x, 0.f), w2.x, p1);
                p1 = fmaf(fmaxf(acc[nc][3] + ai.y + bv1.y, 0.f), w2.y, p1);
            }
        }

        // reduce over the 4-lane h groups and write scores
        p0 += __shfl_xor_sync(0xffffffffu, p0, 1);
        p0 += __shfl_xor_sync(0xffffffffu, p0, 2);
        p1 += __shfl_xor_sync(0xffffffffu, p1, 1);
        p1 += __shfl_xor_sync(0xffffffffu, p1, 2);
        if ((lane & 3) == 0) {
            g_scores[(size_t)(brow + i) * NN + jg0]     = p0;
            g_scores[(size_t)(brow + i) * NN + jg0 + 8] = p1;
        }
    }
}

// ---------------------------------------------------------------------------
// Kernel 3: per-row top-K + outputs (unchanged)
// ---------------------------------------------------------------------------
__global__ void __launch_bounds__(256, 4)
topk_out_kernel(const float* __restrict__ s,
                const int* __restrict__ Kp,
                float* __restrict__ ctx_out,
                float* __restrict__ gate_out,
                float* __restrict__ w_out,
                int writeGW) {
    __shared__ float scoreArr[NN];
    __shared__ float flagArr[NN];
    __shared__ int selIdx[NN];

    const int tid = threadIdx.x;
    const int lane = tid & 31;
    const int warp = tid >> 5;
    const int row = blockIdx.x;
    const int b = row >> 8;

    int kv = 8;
    if (Kp) {
        int raw = *Kp;
        if (raw < 1 || raw > 100000) {
            float f = __int_as_float(raw);
            raw = (int)f;
        }
        kv = raw;
    }
    if (kv > NN) kv = NN;
    if (kv < 0) kv = 0;

    scoreArr[tid] = g_scores[row * NN + tid];
    flagArr[tid] = 0.f;
    __syncthreads();

    if (warp == 0) {
        float v[8];
#pragma unroll
        for (int m = 0; m < 8; m++) v[m] = scoreArr[lane + (m << 5)];
        for (int t = 0; t < kv; t++) {
            float bv = v[0];
            int bm = 0;
#pragma unroll
            for (int m = 1; m < 8; m++)
                if (v[m] > bv) { bv = v[m]; bm = m; }
            int bi = lane + (bm << 5);
#pragma unroll
            for (int off = 16; off > 0; off >>= 1) {
                float ov = __shfl_xor_sync(0xffffffffu, bv, off);
                int   oi = __shfl_xor_sync(0xffffffffu, bi, off);
                if (ov > bv || (ov == bv && oi < bi)) { bv = ov; bi = oi; }
            }
            if (lane == (bi & 31)) v[bi >> 5] = -CUDART_INF_F;
            if (lane == 0) { selIdx[t] = bi; flagArr[bi] = 1.f; }
            __syncwarp();
        }
    }
    __syncthreads();

    float invK = (kv > 0) ? (1.f / (float)kv) : 0.f;
    if (writeGW) {
        float g = flagArr[tid];
        gate_out[row * NN + tid] = g;
        w_out[row * NN + tid] = g * invK;
    }
    if (tid < DD) {
        float a = 0.f;
        for (int t = 0; t < kv; t++) a += s[((b << 8) + selIdx[t]) * DD + tid];
        ctx_out[row * DD + tid] = a * invK;
    }
}

// ---------------------------------------------------------------------------
extern "C" void kernel_launch(void* const* d_in, const int* in_sizes, int n_in,
                              void* d_out, int out_size) {
    const float* s  = (const float*)d_in[0];
    const float* W1 = (const float*)d_in[1];
    const float* b1 = (const float*)d_in[2];
    const float* W2 = (const float*)d_in[3];
    const int* Kp = (n_in > 5) ? (const int*)d_in[5] : nullptr;

    const int n_ctx  = BN * DD;
    const int n_gate = BN * NN;
    float* ctx  = (float*)d_out;
    float* gate = ctx + n_ctx;
    float* wout = gate + n_gate;
    int writeGW = (out_size >= n_ctx + 2 * n_gate) ? 1 : 0;

    cudaFuncSetAttribute(mma_main_kernel,
                         cudaFuncAttributeMaxDynamicSharedMemorySize, SMEM_MAIN);

    precompute_AB_kernel<<<BN / PR, 256>>>(s, W1, b1);
    split_w1c_kernel<<<(DD * HH) / 256, 256>>>(W1);
    mma_main_kernel<<<GRID_MAIN, 256, SMEM_MAIN>>>(s, W2);
    topk_out_kernel<<<BN, 256>>>(s, Kp, ctx, gate, wout, writeGW);
}

// round 11
// speedup vs baseline: 1.0152x; 1.0152x over previous
#include <cuda_runtime.h>
#include <cuda_bf16.h>
#include <math_constants.h>
#include <cstdint>

#define BB 4
#define NN 256
#define DD 128
#define HH 256          // 2*D
#define BN (BB*NN)      // 1024 rows

// ---------------------------------------------------------------------------
// Device scratch
// ---------------------------------------------------------------------------
__device__ float g_Amat[BN * HH];     // A[row,h] = s_row @ W1a + b1
__device__ float g_Bmat[BN * HH];     // B[row,h] = s_row @ W1b
__device__ float g_scores[BB * NN * NN];
__device__ float4 g_Bh_img[4096];     // 64KB: W1c^T hi, [h][d] bf16, seg-swizzled
__device__ float4 g_Bl_img[4096];     // 64KB: lo part

// ---------------------------------------------------------------------------
// helpers
// ---------------------------------------------------------------------------
__device__ __forceinline__ uint32_t smem_u32(const void* p) {
    uint32_t a;
    asm("{ .reg .u64 t; cvta.to.shared.u64 t, %1; cvt.u32.u64 %0, t; }"
        : "=r"(a) : "l"(p));
    return a;
}
__device__ __forceinline__ void ldsm_x4(uint32_t& r0, uint32_t& r1,
                                        uint32_t& r2, uint32_t& r3, uint32_t a) {
    asm volatile("ldmatrix.sync.aligned.m8n8.x4.shared.b16 {%0,%1,%2,%3}, [%4];"
                 : "=r"(r0), "=r"(r1), "=r"(r2), "=r"(r3) : "r"(a));
}
__device__ __forceinline__ void mma16816(float* d, uint32_t a0, uint32_t a1,
                                         uint32_t a2, uint32_t a3,
                                         uint32_t b0, uint32_t b1) {
    asm volatile(
        "mma.sync.aligned.m16n8k16.row.col.f32.bf16.bf16.f32 "
        "{%0,%1,%2,%3}, {%4,%5,%6,%7}, {%8,%9}, {%0,%1,%2,%3};"
        : "+f"(d[0]), "+f"(d[1]), "+f"(d[2]), "+f"(d[3])
        : "r"(a0), "r"(a1), "r"(a2), "r"(a3), "r"(b0), "r"(b1));
}

// ---------------------------------------------------------------------------
// Kernel 1: precompute A,B (proven config)
// ---------------------------------------------------------------------------
#define PR 4
__global__ void __launch_bounds__(256)
precompute_AB_kernel(const float* __restrict__ s,
                     const float* __restrict__ W1,
                     const float* __restrict__ b1) {
    __shared__ float  sv[PR][DD];
    __shared__ float4 WA4[2][16 * 64];
    __shared__ float4 WB4[2][16 * 64];

    const int row0 = blockIdx.x * PR;
    const int tid = threadIdx.x;

    for (int idx = tid; idx < PR * DD; idx += 256)
        sv[idx >> 7][idx & 127] = s[row0 * DD + idx];

    const float bias = b1[tid];
    float a[PR], bb[PR];
#pragma unroll
    for (int r = 0; r < PR; r++) { a[r] = bias; bb[r] = 0.f; }

    const float4* W1_4 = (const float4*)W1;

    float4 pa[4], pb[4];
#pragma unroll
    for (int k = 0; k < 4; k++) {
        int idx = k * 256 + tid;
        int d = idx >> 6, c = idx & 63;
        pa[k] = __ldg(&W1_4[d * 64 + c]);
        pb[k] = __ldg(&W1_4[(DD + d) * 64 + c]);
    }

    for (int ch = 0; ch < 8; ch++) {
        const int buf = ch & 1;
        __syncthreads();
#pragma unroll
        for (int k = 0; k < 4; k++) {
            WA4[buf][k * 256 + tid] = pa[k];
            WB4[buf][k * 256 + tid] = pb[k];
        }
        if (ch < 7) {
            const int d0 = (ch + 1) * 16;
#pragma unroll
            for (int k = 0; k < 4; k++) {
                int idx = k * 256 + tid;
                int d = idx >> 6, c = idx & 63;
                pa[k] = __ldg(&W1_4[(d0 + d) * 64 + c]);
                pb[k] = __ldg(&W1_4[(DD + d0 + d) * 64 + c]);
            }
        }
        __syncthreads();
        const float* WA = (const float*)WA4[buf];
        const float* WB = (const float*)WB4[buf];
        const int d0 = ch * 16;
#pragma unroll
        for (int dd = 0; dd < 16; dd++) {
            float wa = WA[dd * 256 + tid];
            float wb = WB[dd * 256 + tid];
#pragma unroll
            for (int r = 0; r < PR; r++) {
                float sval = sv[r][d0 + dd];
                a[r]  = fmaf(sval, wa, a[r]);
                bb[r] = fmaf(sval, wb, bb[r]);
            }
        }
    }
#pragma unroll
    for (int r = 0; r < PR; r++) {
        g_Amat[(row0 + r) * HH + tid] = a[r];
        g_Bmat[(row0 + r) * HH + tid] = bb[r];
    }
}

// ---------------------------------------------------------------------------
// Kernel 1b: split W1c -> bf16 hi/lo global images, laid out exactly as the
// main kernel's B smem: [h][d] bf16 rows of 256B, 16B segments XOR-swizzled
// by (h&7) so ldmatrix row reads are conflict-free.
// ---------------------------------------------------------------------------
__global__ void __launch_bounds__(256)
split_w1c_kernel(const float* __restrict__ W1) {
    int idx = blockIdx.x * 256 + threadIdx.x;   // 0..32767
    int d = idx >> 8, h = idx & 255;
    float w = W1[(2 * DD + d) * HH + h];
    __nv_bfloat16 hi = __float2bfloat16_rn(w);
    float r = w - __bfloat162float(hi);
    __nv_bfloat16 lo = __float2bfloat16_rn(r);
    uint32_t byte = (uint32_t)h * 256u
                  + (uint32_t)(((d >> 3) ^ (h & 7)) << 4)
                  + (uint32_t)((d & 7) << 1);
    *(__nv_bfloat16*)((char*)g_Bh_img + byte) = hi;
    *(__nv_bfloat16*)((char*)g_Bl_img + byte) = lo;
}

// ---------------------------------------------------------------------------
// Kernel 2: persistent mma.sync bf16 kernel.
// Item = (b, i, jtile): D[j(128), h(256)] = sum_d (s_i*s_j)[d] * W1c[d,h],
// 3 bf16 split passes accumulated in fp32 register fragments
// (Ah*Bh + Ah*Bl + Al*Bh; dropped Al*Bl term <= 2^-18 relative).
// 8 warps x m16 j-tiles; N in two 128-h halves (acc 64 regs).
// B fragments loaded via ldmatrix.x4 (2 n-groups x 2 k-segs per instr) and
// software-pipelined across the nc loop to hide LDSM latency.
// Fused epilogue: score[j] += relu(D + Ai[h] + Bmat[j][h]) * W2[h].
// ---------------------------------------------------------------------------
#define GRID_MAIN 148
#define N_ITEMS   (BB * NN * 2)   // 2048

#define OFF_BH 0          // 65536
#define OFF_BL 65536      // 65536
#define OFF_AH 131072     // 32768
#define OFF_AL 163840     // 32768
#define OFF_AI 196608     // 1024
#define OFF_W2 197632     // 1024
#define OFF_SI 198656     // 512
#define SMEM_MAIN 199168

__global__ void __launch_bounds__(256)
mma_main_kernel(const float* __restrict__ s, const float* __restrict__ W2) {
    extern __shared__ char smc[];
    float* aiS = (float*)(smc + OFF_AI);
    float* w2S = (float*)(smc + OFF_W2);
    float* siS = (float*)(smc + OFF_SI);

    const int tid  = threadIdx.x;
    const int warp = tid >> 5;
    const int lane = tid & 31;
    const int bid  = blockIdx.x;
    const uint32_t sbase = smem_u32(smc);

    // Stage B hi/lo images once (resident across all items)
    {
        float4* bh = (float4*)(smc + OFF_BH);
        float4* bl = (float4*)(smc + OFF_BL);
        for (int k = tid; k < 4096; k += 256) {
            bh[k] = __ldg(&g_Bh_img[k]);
            bl[k] = __ldg(&g_Bl_img[k]);
        }
        w2S[tid] = __ldg(&W2[tid]);
    }
    __syncthreads();

    // ldmatrix lane constants
    const int l7  = lane & 7;
    const int g   = lane >> 3;            // 4 address groups
    const int shA = g >> 1;               // A k-segment select
    const int rowA = warp * 16 + ((g & 1) << 3) + l7;
    const uint32_t aBaseH = sbase + OFF_AH + (uint32_t)rowA * 256u;
    const uint32_t aBaseL = aBaseH + (uint32_t)(OFF_AL - OFF_AH);
    const uint32_t aXor = (uint32_t)l7;
    // B x4: group g: (g>>1) = n-subgroup (8 rows), (g&1) = k-segment
    const uint32_t bBase4H = sbase + OFF_BH + (uint32_t)(g >> 1) * 2048u
                           + (uint32_t)l7 * 256u;
    const uint32_t ksegB = (uint32_t)(g & 1);
    const uint32_t bXor4 = (uint32_t)l7;

    const int n = (N_ITEMS - 1 - bid) / GRID_MAIN + 1;

    for (int u = 0; u < n; u++) {
        const int t  = bid + u * GRID_MAIN;
        const int b  = t >> 9;
        const int i  = (t >> 1) & 255;
        const int jt = t & 1;
        const int brow = b * NN;

        __syncthreads();   // previous item fully consumed
        if (tid < DD) siS[tid] = s[(size_t)(brow + i) * DD + tid];
        aiS[tid] = g_Amat[(size_t)(brow + i) * HH + tid];
        __syncthreads();

        // Stage A = (s_i o s_j) split hi/lo, swizzled. 2 threads per j row.
        {
            const int j  = tid >> 1;
            const int dh = tid & 1;
            const float* srow  = s + (size_t)(brow + jt * 128 + j) * DD + dh * 64;
            const float* sivec = siS + dh * 64;
            const uint32_t rbase = (uint32_t)j * 256u;
            const uint32_t jx = (uint32_t)(j & 7);
#pragma unroll 8
            for (int dp = 0; dp < 32; dp++) {
                const int d = dh * 64 + dp * 2;
                float2 sj = __ldg((const float2*)(srow + dp * 2));
                float2 si = *(const float2*)(sivec + dp * 2);
                float a0 = si.x * sj.x, a1 = si.y * sj.y;
                __nv_bfloat16 h0 = __float2bfloat16_rn(a0);
                __nv_bfloat16 h1 = __float2bfloat16_rn(a1);
                float r0 = a0 - __bfloat162float(h0);
                float r1 = a1 - __bfloat162float(h1);
                uint32_t off = rbase + ((((uint32_t)(d >> 3)) ^ jx) << 4)
                             + (uint32_t)((d & 7) << 1);
                *(__nv_bfloat162*)(smc + OFF_AH + off) = __halves2bfloat162(h0, h1);
                *(__nv_bfloat162*)(smc + OFF_AL + off) =
                    __halves2bfloat162(__float2bfloat16_rn(r0),
                                       __float2bfloat16_rn(r1));
            }
        }
        __syncthreads();

        float p0 = 0.f, p1 = 0.f;
        const int jg0 = jt * 128 + warp * 16 + (lane >> 2);
        const float* bjr0 = g_Bmat + (size_t)(brow + jg0) * HH;
        const float* bjr1 = bjr0 + 8 * HH;

#pragma unroll 1
        for (int half = 0; half < 2; half++) {
            float acc[16][4];
#pragma unroll
            for (int nc = 0; nc < 16; nc++)
#pragma unroll
                for (int q = 0; q < 4; q++) acc[nc][q] = 0.f;

            const uint32_t hOff = (uint32_t)(half * 128) * 256u;

#pragma unroll 1
            for (int kc = 0; kc < 8; kc++) {
                uint32_t ah0, ah1, ah2, ah3, al0, al1, al2, al3;
                const uint32_t aSw = (((uint32_t)(2 * kc + shA)) ^ aXor) << 4;
                ldsm_x4(ah0, ah1, ah2, ah3, aBaseH + aSw);
                ldsm_x4(al0, al1, al2, al3, aBaseL + aSw);

                const uint32_t kSw = (((uint32_t)(2 * kc) + ksegB) ^ bXor4) << 4;
                const uint32_t bRow = bBase4H + hOff + kSw;

                uint32_t cbh[4], cbl[4], nbh[4], nbl[4];
                ldsm_x4(cbh[0], cbh[1], cbh[2], cbh[3], bRow);
                ldsm_x4(cbl[0], cbl[1], cbl[2], cbl[3],
                        bRow + (uint32_t)(OFF_BL - OFF_BH));
#pragma unroll
                for (int ncp = 0; ncp < 8; ncp++) {
                    if (ncp < 7) {
                        const uint32_t nAddr = bRow + (uint32_t)(ncp + 1) * 4096u;
                        ldsm_x4(nbh[0], nbh[1], nbh[2], nbh[3], nAddr);
                        ldsm_x4(nbl[0], nbl[1], nbl[2], nbl[3],
                                nAddr + (uint32_t)(OFF_BL - OFF_BH));
                    }
                    float* a0 = acc[2 * ncp];
                    float* a1 = acc[2 * ncp + 1];
                    mma16816(a0, ah0, ah1, ah2, ah3, cbh[0], cbh[1]);
                    mma16816(a0, ah0, ah1, ah2, ah3, cbl[0], cbl[1]);
                    mma16816(a0, al0, al1, al2, al3, cbh[0], cbh[1]);
                    mma16816(a1, ah0, ah1, ah2, ah3, cbh[2], cbh[3]);
                    mma16816(a1, ah0, ah1, ah2, ah3, cbl[2], cbl[3]);
                    mma16816(a1, al0, al1, al2, al3, cbh[2], cbh[3]);
#pragma unroll
                    for (int q = 0; q < 4; q++) {
                        cbh[q] = nbh[q];
                        cbl[q] = nbl[q];
                    }
                }
            }

            // epilogue for this h-half
            const int hb = half * 128 + 2 * (lane & 3);
#pragma unroll
            for (int nc = 0; nc < 16; nc++) {
                const int h0 = hb + nc * 8;
                float2 ai = *(const float2*)(aiS + h0);
                float2 w2 = *(const float2*)(w2S + h0);
                float2 bv0 = __ldg((const float2*)(bjr0 + h0));
                float2 bv1 = __ldg((const float2*)(bjr1 + h0));
                p0 = fmaf(fmaxf(acc[nc][0] + ai.x + bv0.x, 0.f), w2.x, p0);
                p0 = fmaf(fmaxf(acc[nc][1] + ai.y + bv0.y, 0.f), w2.y, p0);
                p1 = fmaf(fmaxf(acc[nc][2] + ai.x + bv1.x, 0.f), w2.x, p1);
                p1 = fmaf(fmaxf(acc[nc][3] + ai.y + bv1.y, 0.f), w2.y, p1);
            }
        }

        // reduce over the 4-lane h groups and write scores
        p0 += __shfl_xor_sync(0xffffffffu, p0, 1);
        p0 += __shfl_xor_sync(0xffffffffu, p0, 2);
        p1 += __shfl_xor_sync(0xffffffffu, p1, 1);
        p1 += __shfl_xor_sync(0xffffffffu, p1, 2);
        if ((lane & 3) == 0) {
            g_scores[(size_t)(brow + i) * NN + jg0]     = p0;
            g_scores[(size_t)(brow + i) * NN + jg0 + 8] = p1;
        }
    }
}

// ---------------------------------------------------------------------------
// Kernel 3: per-row top-K + outputs (unchanged)
// ---------------------------------------------------------------------------
__global__ void __launch_bounds__(256, 4)
topk_out_kernel(const float* __restrict__ s,
                const int* __restrict__ Kp,
                float* __restrict__ ctx_out,
                float* __restrict__ gate_out,
                float* __restrict__ w_out,
                int writeGW) {
    __shared__ float scoreArr[NN];
    __shared__ float flagArr[NN];
    __shared__ int selIdx[NN];

    const int tid = threadIdx.x;
    const int lane = tid & 31;
    const int warp = tid >> 5;
    const int row = blockIdx.x;
    const int b = row >> 8;

    int kv = 8;
    if (Kp) {
        int raw = *Kp;
        if (raw < 1 || raw > 100000) {
            float f = __int_as_float(raw);
            raw = (int)f;
        }
        kv = raw;
    }
    if (kv > NN) kv = NN;
    if (kv < 0) kv = 0;

    scoreArr[tid] = g_scores[row * NN + tid];
    flagArr[tid] = 0.f;
    __syncthreads();

    if (warp == 0) {
        float v[8];
#pragma unroll
        for (int m = 0; m < 8; m++) v[m] = scoreArr[lane + (m << 5)];
        for (int t = 0; t < kv; t++) {
            float bv = v[0];
            int bm = 0;
#pragma unroll
            for (int m = 1; m < 8; m++)
                if (v[m] > bv) { bv = v[m]; bm = m; }
            int bi = lane + (bm << 5);
#pragma unroll
            for (int off = 16; off > 0; off >>= 1) {
                float ov = __shfl_xor_sync(0xffffffffu, bv, off);
                int   oi = __shfl_xor_sync(0xffffffffu, bi, off);
                if (ov > bv || (ov == bv && oi < bi)) { bv = ov; bi = oi; }
            }
            if (lane == (bi & 31)) v[bi >> 5] = -CUDART_INF_F;
            if (lane == 0) { selIdx[t] = bi; flagArr[bi] = 1.f; }
            __syncwarp();
        }
    }
    __syncthreads();

    float invK = (kv > 0) ? (1.f / (float)kv) : 0.f;
    if (writeGW) {
        float g = flagArr[tid];
        gate_out[row * NN + tid] = g;
        w_out[row * NN + tid] = g * invK;
    }
    if (tid < DD) {
        float a = 0.f;
        for (int t = 0; t < kv; t++) a += s[((b << 8) + selIdx[t]) * DD + tid];
        ctx_out[row * DD + tid] = a * invK;
    }
}

// ---------------------------------------------------------------------------
extern "C" void kernel_launch(void* const* d_in, const int* in_sizes, int n_in,
                              void* d_out, int out_size) {
    const float* s  = (const float*)d_in[0];
    const float* W1 = (const float*)d_in[1];
    const float* b1 = (const float*)d_in[2];
    const float* W2 = (const float*)d_in[3];
    const int* Kp = (n_in > 5) ? (const int*)d_in[5] : nullptr;

    const int n_ctx  = BN * DD;
    const int n_gate = BN * NN;
    float* ctx  = (float*)d_out;
    float* gate = ctx + n_ctx;
    float* wout = gate + n_gate;
    int writeGW = (out_size >= n_ctx + 2 * n_gate) ? 1 : 0;

    cudaFuncSetAttribute(mma_main_kernel,
                         cudaFuncAttributeMaxDynamicSharedMemorySize, SMEM_MAIN);

    precompute_AB_kernel<<<BN / PR, 256>>>(s, W1, b1);
    split_w1c_kernel<<<(DD * HH) / 256, 256>>>(W1);
    mma_main_kernel<<<GRID_MAIN, 256, SMEM_MAIN>>>(s, W2);
    topk_out_kernel<<<BN, 256>>>(s, Kp, ctx, gate, wout, writeGW);
}

// round 12
// speedup vs baseline: 1.4737x; 1.4516x over previous
#include <cuda_runtime.h>
#include <cuda_bf16.h>
#include <math_constants.h>
#include <cstdint>

#define BB 4
#define NN 256
#define DD 128
#define HH 256          // 2*D
#define BN (BB*NN)      // 1024 rows
#define NTILES 16
#define NPAIRT 136      // 16*17/2

// ---------------------------------------------------------------------------
// Device scratch
// ---------------------------------------------------------------------------
__device__ float g_Amat[BN * HH];     // A[row,h] = s_row @ W1a + b1
__device__ float g_Bmat[BN * HH];     // B[row,h] = s_row @ W1b
__device__ float g_scores[BB * NN * NN];
__device__ float4 g_Bh_img[4096];     // 64KB: W1c^T hi, [h][d] bf16, seg-swizzled
__device__ float4 g_Bl_img[4096];     // 64KB: lo part

// ---------------------------------------------------------------------------
// helpers
// ---------------------------------------------------------------------------
__device__ __forceinline__ uint32_t smem_u32(const void* p) {
    uint32_t a;
    asm("{ .reg .u64 t; cvta.to.shared.u64 t, %1; cvt.u32.u64 %0, t; }"
        : "=r"(a) : "l"(p));
    return a;
}
__device__ __forceinline__ void ldsm_x4(uint32_t& r0, uint32_t& r1,
                                        uint32_t& r2, uint32_t& r3, uint32_t a) {
    asm volatile("ldmatrix.sync.aligned.m8n8.x4.shared.b16 {%0,%1,%2,%3}, [%4];"
                 : "=r"(r0), "=r"(r1), "=r"(r2), "=r"(r3) : "r"(a));
}
__device__ __forceinline__ void mma16816(float* d, uint32_t a0, uint32_t a1,
                                         uint32_t a2, uint32_t a3,
                                         uint32_t b0, uint32_t b1) {
    asm volatile(
        "mma.sync.aligned.m16n8k16.row.col.f32.bf16.bf16.f32 "
        "{%0,%1,%2,%3}, {%4,%5,%6,%7}, {%8,%9}, {%0,%1,%2,%3};"
        : "+f"(d[0]), "+f"(d[1]), "+f"(d[2]), "+f"(d[3])
        : "r"(a0), "r"(a1), "r"(a2), "r"(a3), "r"(b0), "r"(b1));
}

// ---------------------------------------------------------------------------
// Kernel 1: precompute A,B (proven config)
// ---------------------------------------------------------------------------
#define PR 4
__global__ void __launch_bounds__(256)
precompute_AB_kernel(const float* __restrict__ s,
                     const float* __restrict__ W1,
                     const float* __restrict__ b1) {
    __shared__ float  sv[PR][DD];
    __shared__ float4 WA4[2][16 * 64];
    __shared__ float4 WB4[2][16 * 64];

    const int row0 = blockIdx.x * PR;
    const int tid = threadIdx.x;

    for (int idx = tid; idx < PR * DD; idx += 256)
        sv[idx >> 7][idx & 127] = s[row0 * DD + idx];

    const float bias = b1[tid];
    float a[PR], bb[PR];
#pragma unroll
    for (int r = 0; r < PR; r++) { a[r] = bias; bb[r] = 0.f; }

    const float4* W1_4 = (const float4*)W1;

    float4 pa[4], pb[4];
#pragma unroll
    for (int k = 0; k < 4; k++) {
        int idx = k * 256 + tid;
        int d = idx >> 6, c = idx & 63;
        pa[k] = __ldg(&W1_4[d * 64 + c]);
        pb[k] = __ldg(&W1_4[(DD + d) * 64 + c]);
    }

    for (int ch = 0; ch < 8; ch++) {
        const int buf = ch & 1;
        __syncthreads();
#pragma unroll
        for (int k = 0; k < 4; k++) {
            WA4[buf][k * 256 + tid] = pa[k];
            WB4[buf][k * 256 + tid] = pb[k];
        }
        if (ch < 7) {
            const int d0 = (ch + 1) * 16;
#pragma unroll
            for (int k = 0; k < 4; k++) {
                int idx = k * 256 + tid;
                int d = idx >> 6, c = idx & 63;
                pa[k] = __ldg(&W1_4[(d0 + d) * 64 + c]);
                pb[k] = __ldg(&W1_4[(DD + d0 + d) * 64 + c]);
            }
        }
        __syncthreads();
        const float* WA = (const float*)WA4[buf];
        const float* WB = (const float*)WB4[buf];
        const int d0 = ch * 16;
#pragma unroll
        for (int dd = 0; dd < 16; dd++) {
            float wa = WA[dd * 256 + tid];
            float wb = WB[dd * 256 + tid];
#pragma unroll
            for (int r = 0; r < PR; r++) {
                float sval = sv[r][d0 + dd];
                a[r]  = fmaf(sval, wa, a[r]);
                bb[r] = fmaf(sval, wb, bb[r]);
            }
        }
    }
#pragma unroll
    for (int r = 0; r < PR; r++) {
        g_Amat[(row0 + r) * HH + tid] = a[r];
        g_Bmat[(row0 + r) * HH + tid] = bb[r];
    }
}

// ---------------------------------------------------------------------------
// Kernel 1b: split W1c -> bf16 hi/lo global images ([h][d] bf16 rows of 256B,
// 16B segments XOR-swizzled by (h&7)).
// ---------------------------------------------------------------------------
__global__ void __launch_bounds__(256)
split_w1c_kernel(const float* __restrict__ W1) {
    int idx = blockIdx.x * 256 + threadIdx.x;   // 0..32767
    int d = idx >> 8, h = idx & 255;
    float w = W1[(2 * DD + d) * HH + h];
    __nv_bfloat16 hi = __float2bfloat16_rn(w);
    float r = w - __bfloat162float(hi);
    __nv_bfloat16 lo = __float2bfloat16_rn(r);
    uint32_t byte = (uint32_t)h * 256u
                  + (uint32_t)(((d >> 3) ^ (h & 7)) << 4)
                  + (uint32_t)((d & 7) << 1);
    *(__nv_bfloat16*)((char*)g_Bh_img + byte) = hi;
    *(__nv_bfloat16*)((char*)g_Bl_img + byte) = lo;
}

// ---------------------------------------------------------------------------
// Kernel 2: persistent SYMMETRIC mma.sync bf16 kernel.
// Item = (b, pair-tile ib<=jb, half): A-tile rows r = ii*16+jj carry
// s_{i0+8*half+ii} o s_{j0+jj}; warp w owns fixed i_w and 16 j's.
// D = A @ W1c via 3 bf16-split passes; epilogue emits score(i_w,j) AND the
// mirror score(j,i_w) from the same accumulators (no mirror on diagonal).
// ---------------------------------------------------------------------------
#define GRID_MAIN 148
#define N_ITEMS   (BB * NPAIRT * 2)   // 1088

#define OFF_BH  0          // 65536
#define OFF_BL  65536      // 65536
#define OFF_AH  131072     // 32768
#define OFF_AL  163840     // 32768
#define OFF_SI  196608     // 4096  : siS[8][128]
#define OFF_AIS 200704     // 8192  : AiS[8][256]
#define OFF_BIS 208896     // 8192  : BiS[8][256]
#define OFF_W2  217088     // 1024
#define SMEM_MAIN 218112

__global__ void __launch_bounds__(256)
mma_main_kernel(const float* __restrict__ s, const float* __restrict__ W2) {
    extern __shared__ char smc[];
    float* siS = (float*)(smc + OFF_SI);
    float* aiS = (float*)(smc + OFF_AIS);
    float* biS = (float*)(smc + OFF_BIS);
    float* w2S = (float*)(smc + OFF_W2);

    const int tid  = threadIdx.x;
    const int warp = tid >> 5;
    const int lane = tid & 31;
    const int bid  = blockIdx.x;
    const uint32_t sbase = smem_u32(smc);

    // Stage B hi/lo images once (resident across all items)
    {
        float4* bh = (float4*)(smc + OFF_BH);
        float4* bl = (float4*)(smc + OFF_BL);
        for (int k = tid; k < 4096; k += 256) {
            bh[k] = __ldg(&g_Bh_img[k]);
            bl[k] = __ldg(&g_Bl_img[k]);
        }
        w2S[tid] = __ldg(&W2[tid]);
    }
    __syncthreads();

    // ldmatrix lane constants
    const int l7  = lane & 7;
    const int g   = lane >> 3;            // 4 address groups
    const int shA = g >> 1;               // A k-segment select
    const int rowA = warp * 16 + ((g & 1) << 3) + l7;
    const uint32_t aBaseH = sbase + OFF_AH + (uint32_t)rowA * 256u;
    const uint32_t aBaseL = aBaseH + (uint32_t)(OFF_AL - OFF_AH);
    const uint32_t aXor = (uint32_t)l7;
    // B x4: group g: (g>>1) = n-subgroup (8 rows), (g&1) = k-segment
    const uint32_t bBase4H = sbase + OFF_BH + (uint32_t)(g >> 1) * 2048u
                           + (uint32_t)l7 * 256u;
    const uint32_t ksegB = (uint32_t)(g & 1);
    const uint32_t bXor4 = (uint32_t)l7;

    const int n = (N_ITEMS - 1 - bid) / GRID_MAIN + 1;

    for (int u = 0; u < n; u++) {
        const int t    = bid + u * GRID_MAIN;
        const int b    = t / (NPAIRT * 2);
        const int rem  = t % (NPAIRT * 2);
        const int pt   = rem >> 1;
        const int half = rem & 1;
        int tp = pt, ib = 0;
        while (tp >= (NTILES - ib)) { tp -= (NTILES - ib); ib++; }
        const int jb = ib + tp;
        const bool mirror = (ib != jb);
        const int i0 = ib * 16 + half * 8;    // 8 i-rows this item
        const int j0 = jb * 16;               // 16 j-rows
        const int brow = b * NN;

        __syncthreads();   // previous item fully consumed
        // stage siS[8][128], AiS[8][256], BiS[8][256]
        for (int idx = tid; idx < 8 * DD; idx += 256)
            siS[idx] = s[(size_t)(brow + i0 + (idx >> 7)) * DD + (idx & 127)];
#pragma unroll
        for (int k = 0; k < 8; k++) {
            int idx = k * 256 + tid;
            int r = idx >> 8, h = idx & 255;
            aiS[idx] = g_Amat[(size_t)(brow + i0 + r) * HH + h];
            biS[idx] = g_Bmat[(size_t)(brow + i0 + r) * HH + h];
        }
        __syncthreads();

        // Stage A-tile: row r=(ii*16+jj): (s_i o s_j) split hi/lo, swizzled.
        {
            const int r  = tid >> 1;       // 0..127
            const int dh = tid & 1;
            const int ii = r >> 4;
            const int jj = r & 15;
            const float* srow  = s + (size_t)(brow + j0 + jj) * DD + dh * 64;
            const float* sivec = siS + ii * 128 + dh * 64;
            const uint32_t rbase = (uint32_t)r * 256u;
            const uint32_t jx = (uint32_t)(r & 7);
#pragma unroll 8
            for (int dp = 0; dp < 32; dp++) {
                const int d = dh * 64 + dp * 2;
                float2 sj = __ldg((const float2*)(srow + dp * 2));
                float2 si = *(const float2*)(sivec + dp * 2);
                float a0 = si.x * sj.x, a1 = si.y * sj.y;
                __nv_bfloat16 h0 = __float2bfloat16_rn(a0);
                __nv_bfloat16 h1 = __float2bfloat16_rn(a1);
                float r0 = a0 - __bfloat162float(h0);
                float r1 = a1 - __bfloat162float(h1);
                uint32_t off = rbase + ((((uint32_t)(d >> 3)) ^ jx) << 4)
                             + (uint32_t)((d & 7) << 1);
                *(__nv_bfloat162*)(smc + OFF_AH + off) = __halves2bfloat162(h0, h1);
                *(__nv_bfloat162*)(smc + OFF_AL + off) =
                    __halves2bfloat162(__float2bfloat16_rn(r0),
                                       __float2bfloat16_rn(r1));
            }
        }
        __syncthreads();

        const int iW = i0 + warp;            // this warp's fixed i (local warp<8)
        const int jl0 = lane >> 2;           // j row (low) within tile
        const float* aiR = aiS + warp * 256;
        const float* biR = biS + warp * 256;
        const float* bj0 = g_Bmat + (size_t)(brow + j0 + jl0) * HH;
        const float* bj1 = bj0 + 8 * HH;
        const float* aj0 = g_Amat + (size_t)(brow + j0 + jl0) * HH;
        const float* aj1 = aj0 + 8 * HH;

        float p0 = 0.f, p1 = 0.f, m0 = 0.f, m1 = 0.f;

#pragma unroll 1
        for (int half2 = 0; half2 < 2; half2++) {
            float acc[16][4];
#pragma unroll
            for (int nc = 0; nc < 16; nc++)
#pragma unroll
                for (int q = 0; q < 4; q++) acc[nc][q] = 0.f;

            const uint32_t hOff = (uint32_t)(half2 * 128) * 256u;

#pragma unroll 1
            for (int kc = 0; kc < 8; kc++) {
                uint32_t ah0, ah1, ah2, ah3, al0, al1, al2, al3;
                const uint32_t aSw = (((uint32_t)(2 * kc + shA)) ^ aXor) << 4;
                ldsm_x4(ah0, ah1, ah2, ah3, aBaseH + aSw);
                ldsm_x4(al0, al1, al2, al3, aBaseL + aSw);

                const uint32_t kSw = (((uint32_t)(2 * kc) + ksegB) ^ bXor4) << 4;
                const uint32_t bRow = bBase4H + hOff + kSw;

                uint32_t cbh[4], cbl[4], nbh[4], nbl[4];
                ldsm_x4(cbh[0], cbh[1], cbh[2], cbh[3], bRow);
                ldsm_x4(cbl[0], cbl[1], cbl[2], cbl[3],
                        bRow + (uint32_t)(OFF_BL - OFF_BH));
#pragma unroll
                for (int ncp = 0; ncp < 8; ncp++) {
                    if (ncp < 7) {
                        const uint32_t nAddr = bRow + (uint32_t)(ncp + 1) * 4096u;
                        ldsm_x4(nbh[0], nbh[1], nbh[2], nbh[3], nAddr);
                        ldsm_x4(nbl[0], nbl[1], nbl[2], nbl[3],
                                nAddr + (uint32_t)(OFF_BL - OFF_BH));
                    }
                    float* a0 = acc[2 * ncp];
                    float* a1 = acc[2 * ncp + 1];
                    mma16816(a0, ah0, ah1, ah2, ah3, cbh[0], cbh[1]);
                    mma16816(a0, ah0, ah1, ah2, ah3, cbl[0], cbl[1]);
                    mma16816(a0, al0, al1, al2, al3, cbh[0], cbh[1]);
                    mma16816(a1, ah0, ah1, ah2, ah3, cbh[2], cbh[3]);
                    mma16816(a1, ah0, ah1, ah2, ah3, cbl[2], cbl[3]);
                    mma16816(a1, al0, al1, al2, al3, cbh[2], cbh[3]);
#pragma unroll
                    for (int q = 0; q < 4; q++) {
                        cbh[q] = nbh[q];
                        cbl[q] = nbl[q];
                    }
                }
            }

            // epilogue for this h-half: forward (i_w, j) and mirror (j, i_w)
            const int hb = half2 * 128 + 2 * (lane & 3);
#pragma unroll
            for (int nc = 0; nc < 16; nc++) {
                const int h0 = hb + nc * 8;
                float2 ai = *(const float2*)(aiR + h0);
                float2 w2 = *(const float2*)(w2S + h0);
                float2 bv0 = __ldg((const float2*)(bj0 + h0));
                float2 bv1 = __ldg((const float2*)(bj1 + h0));
                p0 = fmaf(fmaxf(acc[nc][0] + ai.x + bv0.x, 0.f), w2.x, p0);
                p0 = fmaf(fmaxf(acc[nc][1] + ai.y + bv0.y, 0.f), w2.y, p0);
                p1 = fmaf(fmaxf(acc[nc][2] + ai.x + bv1.x, 0.f), w2.x, p1);
                p1 = fmaf(fmaxf(acc[nc][3] + ai.y + bv1.y, 0.f), w2.y, p1);
                if (mirror) {
                    float2 bi = *(const float2*)(biR + h0);
                    float2 av0 = __ldg((const float2*)(aj0 + h0));
                    float2 av1 = __ldg((const float2*)(aj1 + h0));
                    m0 = fmaf(fmaxf(acc[nc][0] + av0.x + bi.x, 0.f), w2.x, m0);
                    m0 = fmaf(fmaxf(acc[nc][1] + av0.y + bi.y, 0.f), w2.y, m0);
                    m1 = fmaf(fmaxf(acc[nc][2] + av1.x + bi.x, 0.f), w2.x, m1);
                    m1 = fmaf(fmaxf(acc[nc][3] + av1.y + bi.y, 0.f), w2.y, m1);
                }
            }
        }

        // reduce over the 4-lane h groups and write scores
        p0 += __shfl_xor_sync(0xffffffffu, p0, 1);
        p0 += __shfl_xor_sync(0xffffffffu, p0, 2);
        p1 += __shfl_xor_sync(0xffffffffu, p1, 1);
        p1 += __shfl_xor_sync(0xffffffffu, p1, 2);
        m0 += __shfl_xor_sync(0xffffffffu, m0, 1);
        m0 += __shfl_xor_sync(0xffffffffu, m0, 2);
        m1 += __shfl_xor_sync(0xffffffffu, m1, 1);
        m1 += __shfl_xor_sync(0xffffffffu, m1, 2);
        if ((lane & 3) == 0) {
            g_scores[(size_t)(brow + iW) * NN + j0 + jl0]     = p0;
            g_scores[(size_t)(brow + iW) * NN + j0 + jl0 + 8] = p1;
            if (mirror) {
                g_scores[(size_t)(brow + j0 + jl0) * NN + iW]     = m0;
                g_scores[(size_t)(brow + j0 + jl0 + 8) * NN + iW] = m1;
            }
        }
    }
}

// ---------------------------------------------------------------------------
// Kernel 3: per-row top-K + outputs (unchanged)
// ---------------------------------------------------------------------------
__global__ void __launch_bounds__(256, 4)
topk_out_kernel(const float* __restrict__ s,
                const int* __restrict__ Kp,
                float* __restrict__ ctx_out,
                float* __restrict__ gate_out,
                float* __restrict__ w_out,
                int writeGW) {
    __shared__ float scoreArr[NN];
    __shared__ float flagArr[NN];
    __shared__ int selIdx[NN];

    const int tid = threadIdx.x;
    const int lane = tid & 31;
    const int warp = tid >> 5;
    const int row = blockIdx.x;
    const int b = row >> 8;

    int kv = 8;
    if (Kp) {
        int raw = *Kp;
        if (raw < 1 || raw > 100000) {
            float f = __int_as_float(raw);
            raw = (int)f;
        }
        kv = raw;
    }
    if (kv > NN) kv = NN;
    if (kv < 0) kv = 0;

    scoreArr[tid] = g_scores[row * NN + tid];
    flagArr[tid] = 0.f;
    __syncthreads();

    if (warp == 0) {
        float v[8];
#pragma unroll
        for (int m = 0; m < 8; m++) v[m] = scoreArr[lane + (m << 5)];
        for (int t = 0; t < kv; t++) {
            float bv = v[0];
            int bm = 0;
#pragma unroll
            for (int m = 1; m < 8; m++)
                if (v[m] > bv) { bv = v[m]; bm = m; }
            int bi = lane + (bm << 5);
#pragma unroll
            for (int off = 16; off > 0; off >>= 1) {
                float ov = __shfl_xor_sync(0xffffffffu, bv, off);
                int   oi = __shfl_xor_sync(0xffffffffu, bi, off);
                if (ov > bv || (ov == bv && oi < bi)) { bv = ov; bi = oi; }
            }
            if (lane == (bi & 31)) v[bi >> 5] = -CUDART_INF_F;
            if (lane == 0) { selIdx[t] = bi; flagArr[bi] = 1.f; }
            __syncwarp();
        }
    }
    __syncthreads();

    float invK = (kv > 0) ? (1.f / (float)kv) : 0.f;
    if (writeGW) {
        float g = flagArr[tid];
        gate_out[row * NN + tid] = g;
        w_out[row * NN + tid] = g * invK;
    }
    if (tid < DD) {
        float a = 0.f;
        for (int t = 0; t < kv; t++) a += s[((b << 8) + selIdx[t]) * DD + tid];
        ctx_out[row * DD + tid] = a * invK;
    }
}

// ---------------------------------------------------------------------------
extern "C" void kernel_launch(void* const* d_in, const int* in_sizes, int n_in,
                              void* d_out, int out_size) {
    const float* s  = (const float*)d_in[0];
    const float* W1 = (const float*)d_in[1];
    const float* b1 = (const float*)d_in[2];
    const float* W2 = (const float*)d_in[3];
    const int* Kp = (n_in > 5) ? (const int*)d_in[5] : nullptr;

    const int n_ctx  = BN * DD;
    const int n_gate = BN * NN;
    float* ctx  = (float*)d_out;
    float* gate = ctx + n_ctx;
    float* wout = gate + n_gate;
    int writeGW = (out_size >= n_ctx + 2 * n_gate) ? 1 : 0;

    cudaFuncSetAttribute(mma_main_kernel,
                         cudaFuncAttributeMaxDynamicSharedMemorySize, SMEM_MAIN);

    precompute_AB_kernel<<<BN / PR, 256>>>(s, W1, b1);
    split_w1c_kernel<<<(DD * HH) / 256, 256>>>(W1);
    mma_main_kernel<<<GRID_MAIN, 256, SMEM_MAIN>>>(s, W2);
    topk_out_kernel<<<BN, 256>>>(s, Kp, ctx, gate, wout, writeGW);
}